// round 13
// baseline (speedup 1.0000x reference)
#include <cuda_runtime.h>
#include <cuda_bf16.h>
#include <cstdint>

#define NN   10000
#define NE   320000
#define FIN  512
#define F    64

#define MU_OFF  ((size_t)NN * (size_t)NN)
#define STD_OFF (MU_OFF + (size_t)NN * F)

// ---------------- scratch (device globals; no allocation allowed) ----------
__device__ float g_P[NN * F];        // feat @ W1
__device__ float g_h1n[NN * F];      // h1 * rsqrt(deg_out)
__device__ float g_agg[NN * F];      // segment-sum of h1n by dst
__device__ __nv_bfloat16 g_ZA[NN * 192];  // [h | l | h]; B panel reads chunks (0,2,1)
__device__ float g_sout[NN];
__device__ float g_sin[NN];
__device__ int   g_cout[NN];
__device__ int   g_cin[NN];
__device__ int   g_off[NN];
__device__ int   g_cur[NN];
__device__ int   g_esrc[NE];

// ---------------- helpers ----------------------------------------------------
__device__ __forceinline__ uint32_t smem_u32(const void* p) {
    uint32_t a;
    asm("{ .reg .u64 t; cvta.to.shared.u64 t, %1; cvt.u32.u64 %0, t; }" : "=r"(a) : "l"(p));
    return a;
}
__device__ __forceinline__ void ldsm4(uint32_t* r, uint32_t addr) {
    asm volatile("ldmatrix.sync.aligned.m8n8.x4.shared.b16 {%0,%1,%2,%3}, [%4];"
        : "=r"(r[0]), "=r"(r[1]), "=r"(r[2]), "=r"(r[3]) : "r"(addr));
}
__device__ __forceinline__ void mma16816(float* d, const uint32_t* a, const uint32_t* b) {
    asm volatile("mma.sync.aligned.m16n8k16.row.col.f32.bf16.bf16.f32 "
        "{%0,%1,%2,%3},{%4,%5,%6,%7},{%8,%9},{%0,%1,%2,%3};"
        : "+f"(d[0]), "+f"(d[1]), "+f"(d[2]), "+f"(d[3])
        : "r"(a[0]), "r"(a[1]), "r"(a[2]), "r"(a[3]), "r"(b[0]), "r"(b[1]));
}
__device__ __forceinline__ void cpasync16(uint32_t dst, const void* src, int srcsize) {
    asm volatile("cp.async.cg.shared.global [%0], [%1], 16, %2;"
        :: "r"(dst), "l"(src), "r"(srcsize) : "memory");
}
#define CP_COMMIT() asm volatile("cp.async.commit_group;" ::: "memory")
#define CP_WAIT0()  asm volatile("cp.async.wait_group 0;" ::: "memory")

// sigmoid via tanh (1 MUFU): sig(x) = 0.5*tanh(0.5x) + 0.5  (adj kernel only)
__device__ __forceinline__ float sigf(float x) {
    float t;
    asm("tanh.approx.f32 %0, %1;" : "=f"(t) : "f"(x * 0.5f));
    return fmaf(t, 0.5f, 0.5f);
}

// ---------------- graph preprocessing -------------------------------------
__global__ void k_zero() {
    int i = blockIdx.x * blockDim.x + threadIdx.x;
    if (i < NN) { g_cout[i] = 0; g_cin[i] = 0; }
}

__global__ void k_deg(const int* __restrict__ src, const int* __restrict__ dst) {
    int e = (blockIdx.x * blockDim.x + threadIdx.x) * 2;
    if (e < NE) {
        int2 s = *(const int2*)(src + e);
        int2 d = *(const int2*)(dst + e);
        atomicAdd(&g_cout[s.x], 1);
        atomicAdd(&g_cout[s.y], 1);
        atomicAdd(&g_cin[d.x], 1);
        atomicAdd(&g_cin[d.y], 1);
    }
}

__global__ __launch_bounds__(1024) void k_scan() {
    __shared__ int part[1024];
    int t = threadIdx.x;
    const int chunk = (NN + 1023) / 1024;
    int beg = t * chunk;
    int end = beg + chunk; if (end > NN) end = NN;
    int mysum = 0;
    for (int i = beg; i < end && i < NN; i++) mysum += g_cin[i];
    part[t] = mysum;
    __syncthreads();
    for (int d = 1; d < 1024; d <<= 1) {
        int v = (t >= d) ? part[t - d] : 0;
        __syncthreads();
        part[t] += v;
        __syncthreads();
    }
    int prefix = part[t] - mysum;
    for (int i = beg; i < end && i < NN; i++) {
        int c = g_cin[i];
        g_off[i] = prefix;
        g_cur[i] = prefix;
        prefix += c;
        int co = g_cout[i]; if (co < 1) co = 1;
        int ci = g_cin[i];  if (ci < 1) ci = 1;
        g_sout[i] = rsqrtf((float)co);
        g_sin[i]  = rsqrtf((float)ci);
    }
}

__global__ void k_scatter(const int* __restrict__ src, const int* __restrict__ dst) {
    int e = (blockIdx.x * blockDim.x + threadIdx.x) * 2;
    if (e < NE) {
        int2 s = *(const int2*)(src + e);
        int2 d = *(const int2*)(dst + e);
        int p0 = atomicAdd(&g_cur[d.x], 1);
        g_esrc[p0] = s.x;
        int p1 = atomicAdd(&g_cur[d.y], 1);
        g_esrc[p1] = s.y;
    }
}

// ---------------- GEMM1: P = feat @ W1  (10000 x 512 x 64), f32x2 FMA ------
__global__ __launch_bounds__(256) void k_gemm1(const float* __restrict__ feat,
                                               const float* __restrict__ W1) {
    __shared__ float sA[64][68];
    __shared__ float sB[64][64];
    int tid = threadIdx.x;
    int tx = tid & 15, ty = tid >> 4;
    int rowBase = blockIdx.x * 64;
    unsigned long long acc2[4][2] = {};
    for (int kt = 0; kt < FIN; kt += 64) {
#pragma unroll
        for (int it = 0; it < 4; it++) {
            int r = ty + it * 16;
            int gr = rowBase + r;
            float4 v = make_float4(0.f, 0.f, 0.f, 0.f);
            if (gr < NN) v = *(const float4*)(feat + (size_t)gr * FIN + kt + tx * 4);
            *(float4*)&sA[r][tx * 4] = v;
            *(float4*)&sB[r][tx * 4] = *(const float4*)(W1 + (size_t)(kt + r) * F + tx * 4);
        }
        __syncthreads();
#pragma unroll 16
        for (int kk = 0; kk < 64; kk++) {
            float a0 = sA[ty * 4 + 0][kk];
            float a1 = sA[ty * 4 + 1][kk];
            float a2 = sA[ty * 4 + 2][kk];
            float a3 = sA[ty * 4 + 3][kk];
            ulonglong2 bp = *(ulonglong2*)&sB[kk][tx * 4];
            unsigned long long ad0, ad1, ad2, ad3;
            asm("mov.b64 %0, {%1, %1};" : "=l"(ad0) : "f"(a0));
            asm("mov.b64 %0, {%1, %1};" : "=l"(ad1) : "f"(a1));
            asm("mov.b64 %0, {%1, %1};" : "=l"(ad2) : "f"(a2));
            asm("mov.b64 %0, {%1, %1};" : "=l"(ad3) : "f"(a3));
            asm("fma.rn.f32x2 %0, %1, %2, %0;" : "+l"(acc2[0][0]) : "l"(ad0), "l"(bp.x));
            asm("fma.rn.f32x2 %0, %1, %2, %0;" : "+l"(acc2[0][1]) : "l"(ad0), "l"(bp.y));
            asm("fma.rn.f32x2 %0, %1, %2, %0;" : "+l"(acc2[1][0]) : "l"(ad1), "l"(bp.x));
            asm("fma.rn.f32x2 %0, %1, %2, %0;" : "+l"(acc2[1][1]) : "l"(ad1), "l"(bp.y));
            asm("fma.rn.f32x2 %0, %1, %2, %0;" : "+l"(acc2[2][0]) : "l"(ad2), "l"(bp.x));
            asm("fma.rn.f32x2 %0, %1, %2, %0;" : "+l"(acc2[2][1]) : "l"(ad2), "l"(bp.y));
            asm("fma.rn.f32x2 %0, %1, %2, %0;" : "+l"(acc2[3][0]) : "l"(ad3), "l"(bp.x));
            asm("fma.rn.f32x2 %0, %1, %2, %0;" : "+l"(acc2[3][1]) : "l"(ad3), "l"(bp.y));
        }
        __syncthreads();
    }
#pragma unroll
    for (int i = 0; i < 4; i++) {
        int r = rowBase + ty * 4 + i;
        if (r < NN) {
            float v0, v1, v2, v3;
            asm("mov.b64 {%0, %1}, %2;" : "=f"(v0), "=f"(v1) : "l"(acc2[i][0]));
            asm("mov.b64 {%0, %1}, %2;" : "=f"(v2), "=f"(v3) : "l"(acc2[i][1]));
            *(float4*)&g_P[r * F + tx * 4] = make_float4(v0, v1, v2, v3);
        }
    }
}

// ---------------- gather 1: h1n = ((sum sout[s]*P[s]) * sin + b1) * sout ----
__global__ __launch_bounds__(256) void k_gather1(const float* __restrict__ b1) {
    int node = blockIdx.x * 8 + (threadIdx.x >> 5);
    if (node >= NN) return;
    int lane = threadIdx.x & 31;
    int beg = g_off[node];
    int cnt = g_cin[node];
    float a0 = 0.f, a1 = 0.f;
    int j = 0;
    for (; j + 4 <= cnt; j += 4) {
        int s0 = g_esrc[beg + j + 0];
        int s1 = g_esrc[beg + j + 1];
        int s2 = g_esrc[beg + j + 2];
        int s3 = g_esrc[beg + j + 3];
        float w0 = g_sout[s0], w1 = g_sout[s1], w2 = g_sout[s2], w3 = g_sout[s3];
        a0 += w0 * g_P[s0 * F + lane];      a1 += w0 * g_P[s0 * F + 32 + lane];
        a0 += w1 * g_P[s1 * F + lane];      a1 += w1 * g_P[s1 * F + 32 + lane];
        a0 += w2 * g_P[s2 * F + lane];      a1 += w2 * g_P[s2 * F + 32 + lane];
        a0 += w3 * g_P[s3 * F + lane];      a1 += w3 * g_P[s3 * F + 32 + lane];
    }
    for (; j < cnt; j++) {
        int s = g_esrc[beg + j];
        float w = g_sout[s];
        a0 += w * g_P[s * F + lane];
        a1 += w * g_P[s * F + 32 + lane];
    }
    float si = g_sin[node];
    float h0 = a0 * si + b1[lane];
    float h1 = a1 * si + b1[lane + 32];
    float so = g_sout[node];
    g_h1n[node * F + lane]       = h0 * so;
    g_h1n[node * F + 32 + lane]  = h1 * so;
}

// ---------------- gather 2: agg = segment_sum(h1n[src], dst)  (64 cols) -----
__global__ __launch_bounds__(256) void k_gather2() {
    int node = blockIdx.x * 8 + (threadIdx.x >> 5);
    if (node >= NN) return;
    int lane = threadIdx.x & 31;
    int beg = g_off[node];
    int cnt = g_cin[node];
    float a0 = 0.f, a1 = 0.f;
    int j = 0;
    for (; j + 4 <= cnt; j += 4) {
        int s0 = g_esrc[beg + j + 0];
        int s1 = g_esrc[beg + j + 1];
        int s2 = g_esrc[beg + j + 2];
        int s3 = g_esrc[beg + j + 3];
        a0 += g_h1n[s0 * F + lane];      a1 += g_h1n[s0 * F + 32 + lane];
        a0 += g_h1n[s1 * F + lane];      a1 += g_h1n[s1 * F + 32 + lane];
        a0 += g_h1n[s2 * F + lane];      a1 += g_h1n[s2 * F + 32 + lane];
        a0 += g_h1n[s3 * F + lane];      a1 += g_h1n[s3 * F + 32 + lane];
    }
    for (; j < cnt; j++) {
        int s = g_esrc[beg + j];
        a0 += g_h1n[s * F + lane];
        a1 += g_h1n[s * F + 32 + lane];
    }
    g_agg[node * F + lane]      = a0;
    g_agg[node * F + 32 + lane] = a1;
}

// ---------------- proj: [mu|logvar] = agg @ [Wmu|Wstd]; reparam; split ------
__global__ __launch_bounds__(256) void k_proj(const float* __restrict__ eps,
                                              const float* __restrict__ Wmu,
                                              const float* __restrict__ bmu,
                                              const float* __restrict__ Wstd,
                                              const float* __restrict__ bstd,
                                              float* __restrict__ out) {
    __shared__ float sA[64][68];
    __shared__ float sW[64][128];   // reused as sOut after the k-loop
    int tid = threadIdx.x;
    int tx = tid & 15, ty = tid >> 4;
    int rowBase = blockIdx.x * 64;
    {
        int f4c = tid & 31;
        int k0 = tid >> 5;
#pragma unroll
        for (int it = 0; it < 8; it++) {
            int k = k0 + it * 8;
            float4 wv;
            if (f4c < 16) wv = *(const float4*)(Wmu + k * F + f4c * 4);
            else          wv = *(const float4*)(Wstd + k * F + (f4c - 16) * 4);
            *(float4*)&sW[k][f4c * 4] = wv;
        }
    }
#pragma unroll
    for (int it = 0; it < 4; it++) {
        int r = ty + it * 16;
        int gr = rowBase + r;
        float4 v = make_float4(0.f, 0.f, 0.f, 0.f);
        if (gr < NN) v = *(const float4*)&g_agg[gr * F + tx * 4];
        *(float4*)&sA[r][tx * 4] = v;
    }
    __syncthreads();
    float acc[4][8] = {};
#pragma unroll 8
    for (int kk = 0; kk < 64; kk++) {
        float a0 = sA[ty * 4 + 0][kk];
        float a1 = sA[ty * 4 + 1][kk];
        float a2 = sA[ty * 4 + 2][kk];
        float a3 = sA[ty * 4 + 3][kk];
        float4 b0 = *(float4*)&sW[kk][tx * 8];
        float4 b1 = *(float4*)&sW[kk][tx * 8 + 4];
        acc[0][0] += a0 * b0.x; acc[0][1] += a0 * b0.y; acc[0][2] += a0 * b0.z; acc[0][3] += a0 * b0.w;
        acc[0][4] += a0 * b1.x; acc[0][5] += a0 * b1.y; acc[0][6] += a0 * b1.z; acc[0][7] += a0 * b1.w;
        acc[1][0] += a1 * b0.x; acc[1][1] += a1 * b0.y; acc[1][2] += a1 * b0.z; acc[1][3] += a1 * b0.w;
        acc[1][4] += a1 * b1.x; acc[1][5] += a1 * b1.y; acc[1][6] += a1 * b1.z; acc[1][7] += a1 * b1.w;
        acc[2][0] += a2 * b0.x; acc[2][1] += a2 * b0.y; acc[2][2] += a2 * b0.z; acc[2][3] += a2 * b0.w;
        acc[2][4] += a2 * b1.x; acc[2][5] += a2 * b1.y; acc[2][6] += a2 * b1.z; acc[2][7] += a2 * b1.w;
        acc[3][0] += a3 * b0.x; acc[3][1] += a3 * b0.y; acc[3][2] += a3 * b0.z; acc[3][3] += a3 * b0.w;
        acc[3][4] += a3 * b1.x; acc[3][5] += a3 * b1.y; acc[3][6] += a3 * b1.z; acc[3][7] += a3 * b1.w;
    }
    __syncthreads();
    float (*sOut)[128] = (float (*)[128])sW;
#pragma unroll
    for (int i = 0; i < 4; i++) {
        *(float4*)&sOut[ty * 4 + i][tx * 8]     = make_float4(acc[i][0], acc[i][1], acc[i][2], acc[i][3]);
        *(float4*)&sOut[ty * 4 + i][tx * 8 + 4] = make_float4(acc[i][4], acc[i][5], acc[i][6], acc[i][7]);
    }
    __syncthreads();

    int w = tid >> 5;
    int lane = tid & 31;
    float bm0 = bmu[lane], bm1 = bmu[lane + 32];
    float bs0 = bstd[lane], bs1 = bstd[lane + 32];
#pragma unroll
    for (int i = 0; i < 8; i++) {
        int rloc = w * 8 + i;
        int node = rowBase + rloc;
        if (node >= NN) continue;
        float si = g_sin[node];
        float mu0 = sOut[rloc][lane]      * si + bm0;
        float mu1 = sOut[rloc][lane + 32] * si + bm1;
        float sd0 = __expf(sOut[rloc][64 + lane] * si + bs0);
        float sd1 = __expf(sOut[rloc][96 + lane] * si + bs1);
        out[MU_OFF + (size_t)node * F + lane]       = mu0;
        out[MU_OFF + (size_t)node * F + 32 + lane]  = mu1;
        out[STD_OFF + (size_t)node * F + lane]      = sd0;
        out[STD_OFF + (size_t)node * F + 32 + lane] = sd1;
        float z0 = eps[(size_t)node * F + lane]      * sd0 + mu0;
        float z1 = eps[(size_t)node * F + 32 + lane] * sd1 + mu1;
        __nv_bfloat16 h0 = __float2bfloat16_rn(z0);
        __nv_bfloat16 h1 = __float2bfloat16_rn(z1);
        __nv_bfloat16 l0 = __float2bfloat16_rn(z0 - __bfloat162float(h0));
        __nv_bfloat16 l1 = __float2bfloat16_rn(z1 - __bfloat162float(h1));
        __nv_bfloat16* za = &g_ZA[(size_t)node * 192];
        za[lane] = h0;       za[lane + 32] = h1;    // chunk0 = h
        za[64 + lane] = l0;  za[96 + lane] = l1;    // chunk1 = l
        za[128 + lane] = h0; za[160 + lane] = h1;   // chunk2 = h
    }
}

// ---------------- adj = sigmoid(Z Z^T), 128x64 tiles, 3 CTAs/SM -------------
#define KW     192
#define STRDB  400                       // bytes per smem row (200 bf16)
#define TILE_A_BYTES (128 * STRDB)       // 51200
#define TILE_B_BYTES (64 * STRDB)        // 25600
#define ADJ_SMEM (TILE_A_BYTES + TILE_B_BYTES)  // 76800
#define NPAN   79                        // 128-row panels
#define NCOL2  157                       // 64-col half-tiles (157*64 = 10048)
#define NT_HT  6241                      // sum_p (157 - 2p)
#define ADJ_GRID 296
#define ADJ_CHUNK ((NT_HT + ADJ_GRID - 1) / ADJ_GRID)  // 22

// A panel (128 rows): chunks [h|l|h] at offsets 0,128,256.
__device__ __forceinline__ void panelA_cpasync(uint32_t smBase, const char* gBase,
                                               int rowBase, int tid) {
#pragma unroll
    for (int it = 0; it < 24; it++) {
        int idx = tid + it * 128;
        int r = idx / 24;
        int cc = idx - r * 24;
        int chunk = cc >> 3;
        int g = cc & 7;
        int srcOff = (chunk == 0) ? 0 : (chunk == 1) ? 128 : 256;
        int grow = rowBase + r;
        const char* src = gBase + (size_t)grow * 384 + srcOff + g * 16;
        int ss = (grow < NN) ? 16 : 0;
        cpasync16(smBase + r * STRDB + cc * 16, src, ss);
    }
}
// B panel (64 rows): chunks [h|h|l] at offsets 0,256,128.
__device__ __forceinline__ void panelB_cpasync(uint32_t smBase, const char* gBase,
                                               int rowBase, int tid) {
#pragma unroll
    for (int it = 0; it < 12; it++) {
        int idx = tid + it * 128;
        int r = idx / 24;
        int cc = idx - r * 24;
        int chunk = cc >> 3;
        int g = cc & 7;
        int srcOff = (chunk == 0) ? 0 : (chunk == 1) ? 256 : 128;
        int grow = rowBase + r;
        const char* src = gBase + (size_t)grow * 384 + srcOff + g * 16;
        int ss = (grow < NN) ? 16 : 0;
        cpasync16(smBase + r * STRDB + cc * 16, src, ss);
    }
}

__global__ __launch_bounds__(128, 3) void k_adj_hmma(float* __restrict__ out) {
    extern __shared__ char smem[];
    char* smA = smem;
    char* smB = smem + TILE_A_BYTES;
    uint32_t sbA = smem_u32(smA);
    uint32_t sbB = smem_u32(smB);

    int tid = threadIdx.x;
    int wid = tid >> 5, lane = tid & 31;
    int wm = wid & 1;        // row half (64 rows)
    int wn = wid >> 1;       // col half (32 cols)
    int group = lane >> 2;
    int qp = lane & 3;
    int lrow = lane & 15;
    int lkh  = (lane >> 4) * 16;

    int t0 = blockIdx.x * ADJ_CHUNK;
    int t1 = t0 + ADJ_CHUNK; if (t1 > NT_HT) t1 = NT_HT;
    if (t0 >= NT_HT) return;

    // locate starting (p, c2): tiles per panel p = NCOL2 - 2p
    int p = 0, base = 0;
    while (base + (NCOL2 - 2 * p) <= t0) { base += NCOL2 - 2 * p; p++; }
    int c2 = 2 * p + (t0 - base);

    const char* ZA = (const char*)g_ZA;

    panelA_cpasync(sbA, ZA, p * 128, tid);
    panelB_cpasync(sbB, ZA, c2 * 64, tid);
    CP_COMMIT();
    CP_WAIT0();
    __syncthreads();

    for (int t = t0; t < t1; t++) {
        int rb = p * 128, cb = c2 * 64;

        float acc[4][4][4];
#pragma unroll
        for (int mt = 0; mt < 4; mt++)
#pragma unroll
            for (int nt = 0; nt < 4; nt++)
#pragma unroll
                for (int u = 0; u < 4; u++) acc[mt][nt][u] = 0.f;

#pragma unroll
        for (int ks = 0; ks < KW / 16; ks++) {
            int kb = ks * 32;
            uint32_t a[4][4];
#pragma unroll
            for (int mt = 0; mt < 4; mt++) {
                uint32_t addr = sbA + (wm * 64 + mt * 16 + lrow) * STRDB + kb + lkh;
                ldsm4(a[mt], addr);
            }
            uint32_t b[4][2];
#pragma unroll
            for (int bt = 0; bt < 2; bt++) {
                uint32_t tmp[4];
                uint32_t addr = sbB + (wn * 32 + bt * 16 + lrow) * STRDB + kb + lkh;
                ldsm4(tmp, addr);
                b[2 * bt][0] = tmp[0];     b[2 * bt][1] = tmp[2];
                b[2 * bt + 1][0] = tmp[1]; b[2 * bt + 1][1] = tmp[3];
            }
#pragma unroll
            for (int mt = 0; mt < 4; mt++)
#pragma unroll
                for (int nt = 0; nt < 4; nt++)
                    mma16816(acc[mt][nt], a[mt], b[nt]);
        }

        __syncthreads();

        // advance + prefetch next tile panels (overlaps epilogue)
        int np = p, nc2 = c2 + 1;
        if (t + 1 < t1) {
            if (nc2 >= NCOL2) { np = p + 1; nc2 = 2 * np; }
            if (np != p) panelA_cpasync(sbA, ZA, np * 128, tid);
            panelB_cpasync(sbB, ZA, nc2 * 64, tid);
            CP_COMMIT();
        }

        // sigmoid once (single-MUFU tanh form)
#pragma unroll
        for (int mt = 0; mt < 4; mt++)
#pragma unroll
            for (int nt = 0; nt < 4; nt++)
#pragma unroll
                for (int u = 0; u < 4; u++) acc[mt][nt][u] = sigf(acc[mt][nt][u]);

        // direct store (rb, cb)
#pragma unroll
        for (int mt = 0; mt < 4; mt++) {
            int r0 = rb + wm * 64 + mt * 16 + group;
            int r1 = r0 + 8;
            bool ok0 = r0 < NN, ok1 = r1 < NN;
            size_t ro0 = (size_t)r0 * NN, ro1 = (size_t)r1 * NN;
#pragma unroll
            for (int nt = 0; nt < 4; nt++) {
                int col = cb + wn * 32 + nt * 8 + qp * 2;
                if (col < NN) {
                    if (ok0) *(float2*)(out + ro0 + col) = make_float2(acc[mt][nt][0], acc[mt][nt][1]);
                    if (ok1) *(float2*)(out + ro1 + col) = make_float2(acc[mt][nt][2], acc[mt][nt][3]);
                }
            }
        }
        // mirrored store (cb, rb) — skip half-tiles inside the diagonal block
        if (c2 >= 2 * p + 2) {
#pragma unroll
            for (int mt = 0; mt < 4; mt++) {
                int r0 = rb + wm * 64 + mt * 16 + group;
                int r1 = r0 + 8;
                bool ok0 = r0 < NN, ok1 = r1 < NN;
#pragma unroll
                for (int nt = 0; nt < 4; nt++) {
                    int col = cb + wn * 32 + nt * 8 + qp * 2;
                    if (col < NN) {
                        if (ok0) out[(size_t)col * NN + r0] = acc[mt][nt][0];
                        if (ok1) out[(size_t)col * NN + r1] = acc[mt][nt][2];
                    }
                    if (col + 1 < NN) {
                        if (ok0) out[(size_t)(col + 1) * NN + r0] = acc[mt][nt][1];
                        if (ok1) out[(size_t)(col + 1) * NN + r1] = acc[mt][nt][3];
                    }
                }
            }
        }

        p = np; c2 = nc2;
        CP_WAIT0();
        __syncthreads();
    }
}

// ---------------- launcher -------------------------------------------------
extern "C" void kernel_launch(void* const* d_in, const int* in_sizes, int n_in,
                              void* d_out, int out_size) {
    (void)in_sizes; (void)n_in; (void)out_size;
    const float* feat = (const float*)d_in[0];
    const float* eps  = (const float*)d_in[1];
    const int*   src  = (const int*)d_in[2];
    const int*   dst  = (const int*)d_in[3];
    const float* W1   = (const float*)d_in[4];
    const float* b1   = (const float*)d_in[5];
    const float* Wmu  = (const float*)d_in[6];
    const float* bmu  = (const float*)d_in[7];
    const float* Wstd = (const float*)d_in[8];
    const float* bstd = (const float*)d_in[9];
    float* out = (float*)d_out;

    static cudaStream_t s2 = nullptr;
    static cudaEvent_t evF = nullptr, evJ = nullptr;
    if (!s2) {
        cudaStreamCreateWithFlags(&s2, cudaStreamNonBlocking);
        cudaEventCreateWithFlags(&evF, cudaEventDisableTiming);
        cudaEventCreateWithFlags(&evJ, cudaEventDisableTiming);
        cudaFuncSetAttribute(k_adj_hmma, cudaFuncAttributeMaxDynamicSharedMemorySize, ADJ_SMEM);
    }

    // fork: CSR build on s2 runs parallel to gemm1 on the main stream
    cudaEventRecord(evF, 0);
    cudaStreamWaitEvent(s2, evF, 0);
    k_zero<<<(NN + 255) / 256, 256, 0, s2>>>();
    k_deg<<<(NE / 2 + 255) / 256, 256, 0, s2>>>(src, dst);
    k_scan<<<1, 1024, 0, s2>>>();
    k_scatter<<<(NE / 2 + 255) / 256, 256, 0, s2>>>(src, dst);
    cudaEventRecord(evJ, s2);

    k_gemm1<<<(NN + 63) / 64, 256>>>(feat, W1);

    cudaStreamWaitEvent(0, evJ, 0);
    k_gather1<<<(NN + 7) / 8, 256>>>(b1);
    k_gather2<<<(NN + 7) / 8, 256>>>();
    k_proj<<<(NN + 63) / 64, 256>>>(eps, Wmu, bmu, Wstd, bstd, out);
    k_adj_hmma<<<ADJ_GRID, 128, ADJ_SMEM>>>(out);
}

// round 14
// speedup vs baseline: 1.1116x; 1.1116x over previous
#include <cuda_runtime.h>
#include <cuda_bf16.h>
#include <cuda_fp16.h>
#include <cstdint>

#define NN   10000
#define NE   320000
#define FIN  512
#define F    64

#define MU_OFF  ((size_t)NN * (size_t)NN)
#define STD_OFF (MU_OFF + (size_t)NN * F)

// ---------------- scratch (device globals; no allocation allowed) ----------
__device__ float g_P[NN * F];        // feat @ W1
__device__ float g_h1n[NN * F];      // h1 * rsqrt(deg_out)
__device__ float g_agg[NN * F];      // segment-sum of h1n by dst
__device__ __half g_Z[NN * 128];     // [h(64) | l(64)] fp16 split of z
__device__ float g_sout[NN];
__device__ float g_sin[NN];
__device__ int   g_cout[NN];
__device__ int   g_cin[NN];
__device__ int   g_off[NN];
__device__ int   g_cur[NN];
__device__ int   g_esrc[NE];

// ---------------- helpers ----------------------------------------------------
__device__ __forceinline__ uint32_t smem_u32(const void* p) {
    uint32_t a;
    asm("{ .reg .u64 t; cvta.to.shared.u64 t, %1; cvt.u32.u64 %0, t; }" : "=r"(a) : "l"(p));
    return a;
}
__device__ __forceinline__ void ldsm4(uint32_t* r, uint32_t addr) {
    asm volatile("ldmatrix.sync.aligned.m8n8.x4.shared.b16 {%0,%1,%2,%3}, [%4];"
        : "=r"(r[0]), "=r"(r[1]), "=r"(r[2]), "=r"(r[3]) : "r"(addr));
}
// fp16 inputs, fp32 accumulate
__device__ __forceinline__ void mma16816(float* d, const uint32_t* a, const uint32_t* b) {
    asm volatile("mma.sync.aligned.m16n8k16.row.col.f32.f16.f16.f32 "
        "{%0,%1,%2,%3},{%4,%5,%6,%7},{%8,%9},{%0,%1,%2,%3};"
        : "+f"(d[0]), "+f"(d[1]), "+f"(d[2]), "+f"(d[3])
        : "r"(a[0]), "r"(a[1]), "r"(a[2]), "r"(a[3]), "r"(b[0]), "r"(b[1]));
}
__device__ __forceinline__ void cpasync16(uint32_t dst, const void* src, int srcsize) {
    asm volatile("cp.async.cg.shared.global [%0], [%1], 16, %2;"
        :: "r"(dst), "l"(src), "r"(srcsize) : "memory");
}
#define CP_COMMIT() asm volatile("cp.async.commit_group;" ::: "memory")
#define CP_WAIT0()  asm volatile("cp.async.wait_group 0;" ::: "memory")

// sigmoid via tanh (1 MUFU): sig(x) = 0.5*tanh(0.5x) + 0.5  (adj kernel only)
__device__ __forceinline__ float sigf(float x) {
    float t;
    asm("tanh.approx.f32 %0, %1;" : "=f"(t) : "f"(x * 0.5f));
    return fmaf(t, 0.5f, 0.5f);
}

// ---------------- graph preprocessing -------------------------------------
__global__ void k_zero() {
    int i = blockIdx.x * blockDim.x + threadIdx.x;
    if (i < NN) { g_cout[i] = 0; g_cin[i] = 0; }
}

__global__ void k_deg(const int* __restrict__ src, const int* __restrict__ dst) {
    int e = (blockIdx.x * blockDim.x + threadIdx.x) * 2;
    if (e < NE) {
        int2 s = *(const int2*)(src + e);
        int2 d = *(const int2*)(dst + e);
        atomicAdd(&g_cout[s.x], 1);
        atomicAdd(&g_cout[s.y], 1);
        atomicAdd(&g_cin[d.x], 1);
        atomicAdd(&g_cin[d.y], 1);
    }
}

__global__ __launch_bounds__(1024) void k_scan() {
    __shared__ int part[1024];
    int t = threadIdx.x;
    const int chunk = (NN + 1023) / 1024;
    int beg = t * chunk;
    int end = beg + chunk; if (end > NN) end = NN;
    int mysum = 0;
    for (int i = beg; i < end && i < NN; i++) mysum += g_cin[i];
    part[t] = mysum;
    __syncthreads();
    for (int d = 1; d < 1024; d <<= 1) {
        int v = (t >= d) ? part[t - d] : 0;
        __syncthreads();
        part[t] += v;
        __syncthreads();
    }
    int prefix = part[t] - mysum;
    for (int i = beg; i < end && i < NN; i++) {
        int c = g_cin[i];
        g_off[i] = prefix;
        g_cur[i] = prefix;
        prefix += c;
        int co = g_cout[i]; if (co < 1) co = 1;
        int ci = g_cin[i];  if (ci < 1) ci = 1;
        g_sout[i] = rsqrtf((float)co);
        g_sin[i]  = rsqrtf((float)ci);
    }
}

__global__ void k_scatter(const int* __restrict__ src, const int* __restrict__ dst) {
    int e = (blockIdx.x * blockDim.x + threadIdx.x) * 2;
    if (e < NE) {
        int2 s = *(const int2*)(src + e);
        int2 d = *(const int2*)(dst + e);
        int p0 = atomicAdd(&g_cur[d.x], 1);
        g_esrc[p0] = s.x;
        int p1 = atomicAdd(&g_cur[d.y], 1);
        g_esrc[p1] = s.y;
    }
}

// ---------------- GEMM1: P = feat @ W1  (10000 x 512 x 64), f32x2 FMA ------
__global__ __launch_bounds__(256) void k_gemm1(const float* __restrict__ feat,
                                               const float* __restrict__ W1) {
    __shared__ float sA[64][68];
    __shared__ float sB[64][64];
    int tid = threadIdx.x;
    int tx = tid & 15, ty = tid >> 4;
    int rowBase = blockIdx.x * 64;
    unsigned long long acc2[4][2] = {};
    for (int kt = 0; kt < FIN; kt += 64) {
#pragma unroll
        for (int it = 0; it < 4; it++) {
            int r = ty + it * 16;
            int gr = rowBase + r;
            float4 v = make_float4(0.f, 0.f, 0.f, 0.f);
            if (gr < NN) v = *(const float4*)(feat + (size_t)gr * FIN + kt + tx * 4);
            *(float4*)&sA[r][tx * 4] = v;
            *(float4*)&sB[r][tx * 4] = *(const float4*)(W1 + (size_t)(kt + r) * F + tx * 4);
        }
        __syncthreads();
#pragma unroll 16
        for (int kk = 0; kk < 64; kk++) {
            float a0 = sA[ty * 4 + 0][kk];
            float a1 = sA[ty * 4 + 1][kk];
            float a2 = sA[ty * 4 + 2][kk];
            float a3 = sA[ty * 4 + 3][kk];
            ulonglong2 bp = *(ulonglong2*)&sB[kk][tx * 4];
            unsigned long long ad0, ad1, ad2, ad3;
            asm("mov.b64 %0, {%1, %1};" : "=l"(ad0) : "f"(a0));
            asm("mov.b64 %0, {%1, %1};" : "=l"(ad1) : "f"(a1));
            asm("mov.b64 %0, {%1, %1};" : "=l"(ad2) : "f"(a2));
            asm("mov.b64 %0, {%1, %1};" : "=l"(ad3) : "f"(a3));
            asm("fma.rn.f32x2 %0, %1, %2, %0;" : "+l"(acc2[0][0]) : "l"(ad0), "l"(bp.x));
            asm("fma.rn.f32x2 %0, %1, %2, %0;" : "+l"(acc2[0][1]) : "l"(ad0), "l"(bp.y));
            asm("fma.rn.f32x2 %0, %1, %2, %0;" : "+l"(acc2[1][0]) : "l"(ad1), "l"(bp.x));
            asm("fma.rn.f32x2 %0, %1, %2, %0;" : "+l"(acc2[1][1]) : "l"(ad1), "l"(bp.y));
            asm("fma.rn.f32x2 %0, %1, %2, %0;" : "+l"(acc2[2][0]) : "l"(ad2), "l"(bp.x));
            asm("fma.rn.f32x2 %0, %1, %2, %0;" : "+l"(acc2[2][1]) : "l"(ad2), "l"(bp.y));
            asm("fma.rn.f32x2 %0, %1, %2, %0;" : "+l"(acc2[3][0]) : "l"(ad3), "l"(bp.x));
            asm("fma.rn.f32x2 %0, %1, %2, %0;" : "+l"(acc2[3][1]) : "l"(ad3), "l"(bp.y));
        }
        __syncthreads();
    }
#pragma unroll
    for (int i = 0; i < 4; i++) {
        int r = rowBase + ty * 4 + i;
        if (r < NN) {
            float v0, v1, v2, v3;
            asm("mov.b64 {%0, %1}, %2;" : "=f"(v0), "=f"(v1) : "l"(acc2[i][0]));
            asm("mov.b64 {%0, %1}, %2;" : "=f"(v2), "=f"(v3) : "l"(acc2[i][1]));
            *(float4*)&g_P[r * F + tx * 4] = make_float4(v0, v1, v2, v3);
        }
    }
}

// ---------------- gather 1: h1n = ((sum sout[s]*P[s]) * sin + b1) * sout ----
__global__ __launch_bounds__(256) void k_gather1(const float* __restrict__ b1) {
    int node = blockIdx.x * 8 + (threadIdx.x >> 5);
    if (node >= NN) return;
    int lane = threadIdx.x & 31;
    int beg = g_off[node];
    int cnt = g_cin[node];
    float a0 = 0.f, a1 = 0.f;
    int j = 0;
    for (; j + 4 <= cnt; j += 4) {
        int s0 = g_esrc[beg + j + 0];
        int s1 = g_esrc[beg + j + 1];
        int s2 = g_esrc[beg + j + 2];
        int s3 = g_esrc[beg + j + 3];
        float w0 = g_sout[s0], w1 = g_sout[s1], w2 = g_sout[s2], w3 = g_sout[s3];
        a0 += w0 * g_P[s0 * F + lane];      a1 += w0 * g_P[s0 * F + 32 + lane];
        a0 += w1 * g_P[s1 * F + lane];      a1 += w1 * g_P[s1 * F + 32 + lane];
        a0 += w2 * g_P[s2 * F + lane];      a1 += w2 * g_P[s2 * F + 32 + lane];
        a0 += w3 * g_P[s3 * F + lane];      a1 += w3 * g_P[s3 * F + 32 + lane];
    }
    for (; j < cnt; j++) {
        int s = g_esrc[beg + j];
        float w = g_sout[s];
        a0 += w * g_P[s * F + lane];
        a1 += w * g_P[s * F + 32 + lane];
    }
    float si = g_sin[node];
    float h0 = a0 * si + b1[lane];
    float h1 = a1 * si + b1[lane + 32];
    float so = g_sout[node];
    g_h1n[node * F + lane]       = h0 * so;
    g_h1n[node * F + 32 + lane]  = h1 * so;
}

// ---------------- gather 2: agg = segment_sum(h1n[src], dst)  (64 cols) -----
__global__ __launch_bounds__(256) void k_gather2() {
    int node = blockIdx.x * 8 + (threadIdx.x >> 5);
    if (node >= NN) return;
    int lane = threadIdx.x & 31;
    int beg = g_off[node];
    int cnt = g_cin[node];
    float a0 = 0.f, a1 = 0.f;
    int j = 0;
    for (; j + 4 <= cnt; j += 4) {
        int s0 = g_esrc[beg + j + 0];
        int s1 = g_esrc[beg + j + 1];
        int s2 = g_esrc[beg + j + 2];
        int s3 = g_esrc[beg + j + 3];
        a0 += g_h1n[s0 * F + lane];      a1 += g_h1n[s0 * F + 32 + lane];
        a0 += g_h1n[s1 * F + lane];      a1 += g_h1n[s1 * F + 32 + lane];
        a0 += g_h1n[s2 * F + lane];      a1 += g_h1n[s2 * F + 32 + lane];
        a0 += g_h1n[s3 * F + lane];      a1 += g_h1n[s3 * F + 32 + lane];
    }
    for (; j < cnt; j++) {
        int s = g_esrc[beg + j];
        a0 += g_h1n[s * F + lane];
        a1 += g_h1n[s * F + 32 + lane];
    }
    g_agg[node * F + lane]      = a0;
    g_agg[node * F + 32 + lane] = a1;
}

// ---------------- proj: [mu|logvar] = agg @ [Wmu|Wstd]; reparam; fp16 split -
__global__ __launch_bounds__(256) void k_proj(const float* __restrict__ eps,
                                              const float* __restrict__ Wmu,
                                              const float* __restrict__ bmu,
                                              const float* __restrict__ Wstd,
                                              const float* __restrict__ bstd,
                                              float* __restrict__ out) {
    __shared__ float sA[64][68];
    __shared__ float sW[64][128];   // reused as sOut after the k-loop
    int tid = threadIdx.x;
    int tx = tid & 15, ty = tid >> 4;
    int rowBase = blockIdx.x * 64;
    {
        int f4c = tid & 31;
        int k0 = tid >> 5;
#pragma unroll
        for (int it = 0; it < 8; it++) {
            int k = k0 + it * 8;
            float4 wv;
            if (f4c < 16) wv = *(const float4*)(Wmu + k * F + f4c * 4);
            else          wv = *(const float4*)(Wstd + k * F + (f4c - 16) * 4);
            *(float4*)&sW[k][f4c * 4] = wv;
        }
    }
#pragma unroll
    for (int it = 0; it < 4; it++) {
        int r = ty + it * 16;
        int gr = rowBase + r;
        float4 v = make_float4(0.f, 0.f, 0.f, 0.f);
        if (gr < NN) v = *(const float4*)&g_agg[gr * F + tx * 4];
        *(float4*)&sA[r][tx * 4] = v;
    }
    __syncthreads();
    float acc[4][8] = {};
#pragma unroll 8
    for (int kk = 0; kk < 64; kk++) {
        float a0 = sA[ty * 4 + 0][kk];
        float a1 = sA[ty * 4 + 1][kk];
        float a2 = sA[ty * 4 + 2][kk];
        float a3 = sA[ty * 4 + 3][kk];
        float4 b0 = *(float4*)&sW[kk][tx * 8];
        float4 b1 = *(float4*)&sW[kk][tx * 8 + 4];
        acc[0][0] += a0 * b0.x; acc[0][1] += a0 * b0.y; acc[0][2] += a0 * b0.z; acc[0][3] += a0 * b0.w;
        acc[0][4] += a0 * b1.x; acc[0][5] += a0 * b1.y; acc[0][6] += a0 * b1.z; acc[0][7] += a0 * b1.w;
        acc[1][0] += a1 * b0.x; acc[1][1] += a1 * b0.y; acc[1][2] += a1 * b0.z; acc[1][3] += a1 * b0.w;
        acc[1][4] += a1 * b1.x; acc[1][5] += a1 * b1.y; acc[1][6] += a1 * b1.z; acc[1][7] += a1 * b1.w;
        acc[2][0] += a2 * b0.x; acc[2][1] += a2 * b0.y; acc[2][2] += a2 * b0.z; acc[2][3] += a2 * b0.w;
        acc[2][4] += a2 * b1.x; acc[2][5] += a2 * b1.y; acc[2][6] += a2 * b1.z; acc[2][7] += a2 * b1.w;
        acc[3][0] += a3 * b0.x; acc[3][1] += a3 * b0.y; acc[3][2] += a3 * b0.z; acc[3][3] += a3 * b0.w;
        acc[3][4] += a3 * b1.x; acc[3][5] += a3 * b1.y; acc[3][6] += a3 * b1.z; acc[3][7] += a3 * b1.w;
    }
    __syncthreads();
    float (*sOut)[128] = (float (*)[128])sW;
#pragma unroll
    for (int i = 0; i < 4; i++) {
        *(float4*)&sOut[ty * 4 + i][tx * 8]     = make_float4(acc[i][0], acc[i][1], acc[i][2], acc[i][3]);
        *(float4*)&sOut[ty * 4 + i][tx * 8 + 4] = make_float4(acc[i][4], acc[i][5], acc[i][6], acc[i][7]);
    }
    __syncthreads();

    int w = tid >> 5;
    int lane = tid & 31;
    float bm0 = bmu[lane], bm1 = bmu[lane + 32];
    float bs0 = bstd[lane], bs1 = bstd[lane + 32];
#pragma unroll
    for (int i = 0; i < 8; i++) {
        int rloc = w * 8 + i;
        int node = rowBase + rloc;
        if (node >= NN) continue;
        float si = g_sin[node];
        float mu0 = sOut[rloc][lane]      * si + bm0;
        float mu1 = sOut[rloc][lane + 32] * si + bm1;
        float sd0 = __expf(sOut[rloc][64 + lane] * si + bs0);
        float sd1 = __expf(sOut[rloc][96 + lane] * si + bs1);
        out[MU_OFF + (size_t)node * F + lane]       = mu0;
        out[MU_OFF + (size_t)node * F + 32 + lane]  = mu1;
        out[STD_OFF + (size_t)node * F + lane]      = sd0;
        out[STD_OFF + (size_t)node * F + 32 + lane] = sd1;
        float z0 = eps[(size_t)node * F + lane]      * sd0 + mu0;
        float z1 = eps[(size_t)node * F + 32 + lane] * sd1 + mu1;
        __half h0 = __float2half_rn(z0);
        __half h1 = __float2half_rn(z1);
        __half l0 = __float2half_rn(z0 - __half2float(h0));
        __half l1 = __float2half_rn(z1 - __half2float(h1));
        __half* zr = &g_Z[(size_t)node * 128];
        zr[lane] = h0;       zr[lane + 32] = h1;    // chunk0 = h
        zr[64 + lane] = l0;  zr[96 + lane] = l1;    // chunk1 = l
    }
}

// ---------------- adj = sigmoid(Z Z^T), fp16x2, symmetric, persistent -------
#define KW     128
#define STRDB  272                       // bytes per smem row (256 data + 16 pad)
#define TILE_BYTES (128 * STRDB)         // 34816 B
#define ADJ_SMEM   (2 * TILE_BYTES)      // 69632 B
#define NPAN   79
#define NT_UT  (NPAN * (NPAN + 1) / 2)   // 3160
#define ADJ_GRID 296
#define ADJ_CHUNK ((NT_UT + ADJ_GRID - 1) / ADJ_GRID)  // 11

// A panel: chunks [h|l] at source offsets 0,128. B panel: [h|h] at 0,0.
__device__ __forceinline__ void panel_cpasync(uint32_t smBase, const char* gBase,
                                              int rowBase, int tid,
                                              int off0, int off1) {
#pragma unroll
    for (int it = 0; it < 16; it++) {
        int idx = tid + it * 128;
        int r = idx >> 4;
        int cc = idx & 15;
        int srcOff = (cc < 8) ? off0 : off1;
        int g = cc & 7;
        int grow = rowBase + r;
        const char* src = gBase + (size_t)grow * 256 + srcOff + g * 16;
        int ss = (grow < NN) ? 16 : 0;
        cpasync16(smBase + r * STRDB + cc * 16, src, ss);
    }
}

__global__ __launch_bounds__(128, 2) void k_adj_hmma(float* __restrict__ out) {
    extern __shared__ char smem[];
    char* smA = smem;
    char* smB = smem + TILE_BYTES;
    uint32_t sbA = smem_u32(smA);
    uint32_t sbB = smem_u32(smB);

    int tid = threadIdx.x;
    int wid = tid >> 5, lane = tid & 31;
    int wm = wid & 1;
    int wn = wid >> 1;
    int group = lane >> 2;
    int qp = lane & 3;
    int lrow = lane & 15;
    int lkh  = (lane >> 4) * 16;

    int t0 = blockIdx.x * ADJ_CHUNK;
    int t1 = t0 + ADJ_CHUNK; if (t1 > NT_UT) t1 = NT_UT;
    if (t0 >= NT_UT) return;

    int p = 0, base = 0;
    while (base + (NPAN - p) <= t0) { base += NPAN - p; p++; }
    int c = p + (t0 - base);

    const char* Z = (const char*)g_Z;

    panel_cpasync(sbA, Z, p * 128, tid, 0, 128);   // [h|l]
    panel_cpasync(sbB, Z, c * 128, tid, 0, 0);     // [h|h]
    CP_COMMIT();
    CP_WAIT0();
    __syncthreads();

    for (int t = t0; t < t1; t++) {
        int rb = p * 128, cb = c * 128;

        float acc[4][8][4];
#pragma unroll
        for (int mt = 0; mt < 4; mt++)
#pragma unroll
            for (int nt = 0; nt < 8; nt++)
#pragma unroll
                for (int u = 0; u < 4; u++) acc[mt][nt][u] = 0.f;

#pragma unroll
        for (int ks = 0; ks < KW / 16; ks++) {
            int kb = ks * 32;
            uint32_t a[4][4];
#pragma unroll
            for (int mt = 0; mt < 4; mt++) {
                uint32_t addr = sbA + (wm * 64 + mt * 16 + lrow) * STRDB + kb + lkh;
                ldsm4(a[mt], addr);
            }
            uint32_t b[8][2];
#pragma unroll
            for (int bt = 0; bt < 4; bt++) {
                uint32_t tmp[4];
                uint32_t addr = sbB + (wn * 64 + bt * 16 + lrow) * STRDB + kb + lkh;
                ldsm4(tmp, addr);
                b[2 * bt][0] = tmp[0];     b[2 * bt][1] = tmp[2];
                b[2 * bt + 1][0] = tmp[1]; b[2 * bt + 1][1] = tmp[3];
            }
#pragma unroll
            for (int mt = 0; mt < 4; mt++)
#pragma unroll
                for (int nt = 0; nt < 8; nt++)
                    mma16816(acc[mt][nt], a[mt], b[nt]);
        }

        __syncthreads();

        int np = p, nc = c + 1;
        if (t + 1 < t1) {
            if (nc >= NPAN) { np = p + 1; nc = np; }
            if (np != p) panel_cpasync(sbA, Z, np * 128, tid, 0, 128);
            panel_cpasync(sbB, Z, nc * 128, tid, 0, 0);
            CP_COMMIT();
        }

        // sigmoid once (single-MUFU tanh form)
#pragma unroll
        for (int mt = 0; mt < 4; mt++)
#pragma unroll
            for (int nt = 0; nt < 8; nt++)
#pragma unroll
                for (int u = 0; u < 4; u++) acc[mt][nt][u] = sigf(acc[mt][nt][u]);

        // direct store (rb, cb)
#pragma unroll
        for (int mt = 0; mt < 4; mt++) {
            int r0 = rb + wm * 64 + mt * 16 + group;
            int r1 = r0 + 8;
            bool ok0 = r0 < NN, ok1 = r1 < NN;
            size_t ro0 = (size_t)r0 * NN, ro1 = (size_t)r1 * NN;
#pragma unroll
            for (int nt = 0; nt < 8; nt++) {
                int col = cb + wn * 64 + nt * 8 + qp * 2;
                if (col < NN) {
                    if (ok0) *(float2*)(out + ro0 + col) = make_float2(acc[mt][nt][0], acc[mt][nt][1]);
                    if (ok1) *(float2*)(out + ro1 + col) = make_float2(acc[mt][nt][2], acc[mt][nt][3]);
                }
            }
        }
        // mirrored store (cb, rb)
        if (p != c) {
#pragma unroll
            for (int mt = 0; mt < 4; mt++) {
                int r0 = rb + wm * 64 + mt * 16 + group;
                int r1 = r0 + 8;
                bool ok0 = r0 < NN, ok1 = r1 < NN;
#pragma unroll
                for (int nt = 0; nt < 8; nt++) {
                    int col = cb + wn * 64 + nt * 8 + qp * 2;
                    if (col < NN) {
                        if (ok0) out[(size_t)col * NN + r0] = acc[mt][nt][0];
                        if (ok1) out[(size_t)col * NN + r1] = acc[mt][nt][2];
                    }
                    if (col + 1 < NN) {
                        if (ok0) out[(size_t)(col + 1) * NN + r0] = acc[mt][nt][1];
                        if (ok1) out[(size_t)(col + 1) * NN + r1] = acc[mt][nt][3];
                    }
                }
            }
        }

        p = np; c = nc;
        CP_WAIT0();
        __syncthreads();
    }
}

// ---------------- launcher -------------------------------------------------
extern "C" void kernel_launch(void* const* d_in, const int* in_sizes, int n_in,
                              void* d_out, int out_size) {
    (void)in_sizes; (void)n_in; (void)out_size;
    const float* feat = (const float*)d_in[0];
    const float* eps  = (const float*)d_in[1];
    const int*   src  = (const int*)d_in[2];
    const int*   dst  = (const int*)d_in[3];
    const float* W1   = (const float*)d_in[4];
    const float* b1   = (const float*)d_in[5];
    const float* Wmu  = (const float*)d_in[6];
    const float* bmu  = (const float*)d_in[7];
    const float* Wstd = (const float*)d_in[8];
    const float* bstd = (const float*)d_in[9];
    float* out = (float*)d_out;

    static cudaStream_t s2 = nullptr;
    static cudaEvent_t evF = nullptr, evJ = nullptr;
    if (!s2) {
        cudaStreamCreateWithFlags(&s2, cudaStreamNonBlocking);
        cudaEventCreateWithFlags(&evF, cudaEventDisableTiming);
        cudaEventCreateWithFlags(&evJ, cudaEventDisableTiming);
        cudaFuncSetAttribute(k_adj_hmma, cudaFuncAttributeMaxDynamicSharedMemorySize, ADJ_SMEM);
    }

    // fork: CSR build on s2 runs parallel to gemm1 on the main stream
    cudaEventRecord(evF, 0);
    cudaStreamWaitEvent(s2, evF, 0);
    k_zero<<<(NN + 255) / 256, 256, 0, s2>>>();
    k_deg<<<(NE / 2 + 255) / 256, 256, 0, s2>>>(src, dst);
    k_scan<<<1, 1024, 0, s2>>>();
    k_scatter<<<(NE / 2 + 255) / 256, 256, 0, s2>>>(src, dst);
    cudaEventRecord(evJ, s2);

    k_gemm1<<<(NN + 63) / 64, 256>>>(feat, W1);

    cudaStreamWaitEvent(0, evJ, 0);
    k_gather1<<<(NN + 7) / 8, 256>>>(b1);
    k_gather2<<<(NN + 7) / 8, 256>>>();
    k_proj<<<(NN + 63) / 64, 256>>>(eps, Wmu, bmu, Wstd, bstd, out);
    k_adj_hmma<<<ADJ_GRID, 128, ADJ_SMEM>>>(out);
}

// round 15
// speedup vs baseline: 1.1797x; 1.0613x over previous
#include <cuda_runtime.h>
#include <cuda_bf16.h>
#include <cuda_fp16.h>
#include <cstdint>

#define NN   10000
#define NE   320000
#define FIN  512
#define F    64

#define MU_OFF  ((size_t)NN * (size_t)NN)
#define STD_OFF (MU_OFF + (size_t)NN * F)

// ---------------- scratch (device globals; no allocation allowed) ----------
__device__ float g_P[NN * F];        // feat @ W1
__device__ float g_h1n[NN * F];      // h1 * rsqrt(deg_out)
__device__ float g_agg[NN * F];      // segment-sum of h1n by dst
__device__ __half g_Z[NN * 128];     // [h(64) | l(64)] fp16 split of z
__device__ float g_sout[NN];
__device__ float g_sin[NN];
__device__ int   g_cout[NN];
__device__ int   g_cin[NN];
__device__ int   g_off[NN];
__device__ int   g_cur[NN];
__device__ int   g_esrc[NE];

// ---------------- helpers ----------------------------------------------------
__device__ __forceinline__ uint32_t smem_u32(const void* p) {
    uint32_t a;
    asm("{ .reg .u64 t; cvta.to.shared.u64 t, %1; cvt.u32.u64 %0, t; }" : "=r"(a) : "l"(p));
    return a;
}
__device__ __forceinline__ void ldsm4(uint32_t* r, uint32_t addr) {
    asm volatile("ldmatrix.sync.aligned.m8n8.x4.shared.b16 {%0,%1,%2,%3}, [%4];"
        : "=r"(r[0]), "=r"(r[1]), "=r"(r[2]), "=r"(r[3]) : "r"(addr));
}
// fp16 inputs, fp32 accumulate
__device__ __forceinline__ void mma16816(float* d, const uint32_t* a, const uint32_t* b) {
    asm volatile("mma.sync.aligned.m16n8k16.row.col.f32.f16.f16.f32 "
        "{%0,%1,%2,%3},{%4,%5,%6,%7},{%8,%9},{%0,%1,%2,%3};"
        : "+f"(d[0]), "+f"(d[1]), "+f"(d[2]), "+f"(d[3])
        : "r"(a[0]), "r"(a[1]), "r"(a[2]), "r"(a[3]), "r"(b[0]), "r"(b[1]));
}
__device__ __forceinline__ void cpasync16(uint32_t dst, const void* src, int srcsize) {
    asm volatile("cp.async.cg.shared.global [%0], [%1], 16, %2;"
        :: "r"(dst), "l"(src), "r"(srcsize) : "memory");
}
#define CP_COMMIT() asm volatile("cp.async.commit_group;" ::: "memory")
#define CP_WAIT0()  asm volatile("cp.async.wait_group 0;" ::: "memory")

// sigmoid via tanh (1 MUFU): sig(x) = 0.5*tanh(0.5x) + 0.5  (adj kernel only)
__device__ __forceinline__ float sigf(float x) {
    float t;
    asm("tanh.approx.f32 %0, %1;" : "=f"(t) : "f"(x * 0.5f));
    return fmaf(t, 0.5f, 0.5f);
}

// ---------------- graph preprocessing -------------------------------------
__global__ void k_zero() {
    int i = blockIdx.x * blockDim.x + threadIdx.x;
    if (i < NN) { g_cout[i] = 0; g_cin[i] = 0; }
}

__global__ void k_deg(const int* __restrict__ src, const int* __restrict__ dst) {
    int e = (blockIdx.x * blockDim.x + threadIdx.x) * 2;
    if (e < NE) {
        int2 s = *(const int2*)(src + e);
        int2 d = *(const int2*)(dst + e);
        atomicAdd(&g_cout[s.x], 1);
        atomicAdd(&g_cout[s.y], 1);
        atomicAdd(&g_cin[d.x], 1);
        atomicAdd(&g_cin[d.y], 1);
    }
}

__global__ __launch_bounds__(1024) void k_scan() {
    __shared__ int part[1024];
    int t = threadIdx.x;
    const int chunk = (NN + 1023) / 1024;
    int beg = t * chunk;
    int end = beg + chunk; if (end > NN) end = NN;
    int mysum = 0;
    for (int i = beg; i < end && i < NN; i++) mysum += g_cin[i];
    part[t] = mysum;
    __syncthreads();
    for (int d = 1; d < 1024; d <<= 1) {
        int v = (t >= d) ? part[t - d] : 0;
        __syncthreads();
        part[t] += v;
        __syncthreads();
    }
    int prefix = part[t] - mysum;
    for (int i = beg; i < end && i < NN; i++) {
        int c = g_cin[i];
        g_off[i] = prefix;
        g_cur[i] = prefix;
        prefix += c;
        int co = g_cout[i]; if (co < 1) co = 1;
        int ci = g_cin[i];  if (ci < 1) ci = 1;
        g_sout[i] = rsqrtf((float)co);
        g_sin[i]  = rsqrtf((float)ci);
    }
}

__global__ void k_scatter(const int* __restrict__ src, const int* __restrict__ dst) {
    int e = (blockIdx.x * blockDim.x + threadIdx.x) * 2;
    if (e < NE) {
        int2 s = *(const int2*)(src + e);
        int2 d = *(const int2*)(dst + e);
        int p0 = atomicAdd(&g_cur[d.x], 1);
        g_esrc[p0] = s.x;
        int p1 = atomicAdd(&g_cur[d.y], 1);
        g_esrc[p1] = s.y;
    }
}

// ---------------- GEMM1: P = feat @ W1  (10000 x 512 x 64), f32x2 FMA ------
__global__ __launch_bounds__(256) void k_gemm1(const float* __restrict__ feat,
                                               const float* __restrict__ W1) {
    __shared__ float sA[64][68];
    __shared__ float sB[64][64];
    int tid = threadIdx.x;
    int tx = tid & 15, ty = tid >> 4;
    int rowBase = blockIdx.x * 64;
    unsigned long long acc2[4][2] = {};
    for (int kt = 0; kt < FIN; kt += 64) {
#pragma unroll
        for (int it = 0; it < 4; it++) {
            int r = ty + it * 16;
            int gr = rowBase + r;
            float4 v = make_float4(0.f, 0.f, 0.f, 0.f);
            if (gr < NN) v = *(const float4*)(feat + (size_t)gr * FIN + kt + tx * 4);
            *(float4*)&sA[r][tx * 4] = v;
            *(float4*)&sB[r][tx * 4] = *(const float4*)(W1 + (size_t)(kt + r) * F + tx * 4);
        }
        __syncthreads();
#pragma unroll 16
        for (int kk = 0; kk < 64; kk++) {
            float a0 = sA[ty * 4 + 0][kk];
            float a1 = sA[ty * 4 + 1][kk];
            float a2 = sA[ty * 4 + 2][kk];
            float a3 = sA[ty * 4 + 3][kk];
            ulonglong2 bp = *(ulonglong2*)&sB[kk][tx * 4];
            unsigned long long ad0, ad1, ad2, ad3;
            asm("mov.b64 %0, {%1, %1};" : "=l"(ad0) : "f"(a0));
            asm("mov.b64 %0, {%1, %1};" : "=l"(ad1) : "f"(a1));
            asm("mov.b64 %0, {%1, %1};" : "=l"(ad2) : "f"(a2));
            asm("mov.b64 %0, {%1, %1};" : "=l"(ad3) : "f"(a3));
            asm("fma.rn.f32x2 %0, %1, %2, %0;" : "+l"(acc2[0][0]) : "l"(ad0), "l"(bp.x));
            asm("fma.rn.f32x2 %0, %1, %2, %0;" : "+l"(acc2[0][1]) : "l"(ad0), "l"(bp.y));
            asm("fma.rn.f32x2 %0, %1, %2, %0;" : "+l"(acc2[1][0]) : "l"(ad1), "l"(bp.x));
            asm("fma.rn.f32x2 %0, %1, %2, %0;" : "+l"(acc2[1][1]) : "l"(ad1), "l"(bp.y));
            asm("fma.rn.f32x2 %0, %1, %2, %0;" : "+l"(acc2[2][0]) : "l"(ad2), "l"(bp.x));
            asm("fma.rn.f32x2 %0, %1, %2, %0;" : "+l"(acc2[2][1]) : "l"(ad2), "l"(bp.y));
            asm("fma.rn.f32x2 %0, %1, %2, %0;" : "+l"(acc2[3][0]) : "l"(ad3), "l"(bp.x));
            asm("fma.rn.f32x2 %0, %1, %2, %0;" : "+l"(acc2[3][1]) : "l"(ad3), "l"(bp.y));
        }
        __syncthreads();
    }
#pragma unroll
    for (int i = 0; i < 4; i++) {
        int r = rowBase + ty * 4 + i;
        if (r < NN) {
            float v0, v1, v2, v3;
            asm("mov.b64 {%0, %1}, %2;" : "=f"(v0), "=f"(v1) : "l"(acc2[i][0]));
            asm("mov.b64 {%0, %1}, %2;" : "=f"(v2), "=f"(v3) : "l"(acc2[i][1]));
            *(float4*)&g_P[r * F + tx * 4] = make_float4(v0, v1, v2, v3);
        }
    }
}

// ---------------- gather 1: h1n = ((sum sout[s]*P[s]) * sin + b1) * sout ----
__global__ __launch_bounds__(256) void k_gather1(const float* __restrict__ b1) {
    int node = blockIdx.x * 8 + (threadIdx.x >> 5);
    if (node >= NN) return;
    int lane = threadIdx.x & 31;
    int beg = g_off[node];
    int cnt = g_cin[node];
    float a0 = 0.f, a1 = 0.f;
    int j = 0;
    for (; j + 4 <= cnt; j += 4) {
        int s0 = g_esrc[beg + j + 0];
        int s1 = g_esrc[beg + j + 1];
        int s2 = g_esrc[beg + j + 2];
        int s3 = g_esrc[beg + j + 3];
        float w0 = g_sout[s0], w1 = g_sout[s1], w2 = g_sout[s2], w3 = g_sout[s3];
        a0 += w0 * g_P[s0 * F + lane];      a1 += w0 * g_P[s0 * F + 32 + lane];
        a0 += w1 * g_P[s1 * F + lane];      a1 += w1 * g_P[s1 * F + 32 + lane];
        a0 += w2 * g_P[s2 * F + lane];      a1 += w2 * g_P[s2 * F + 32 + lane];
        a0 += w3 * g_P[s3 * F + lane];      a1 += w3 * g_P[s3 * F + 32 + lane];
    }
    for (; j < cnt; j++) {
        int s = g_esrc[beg + j];
        float w = g_sout[s];
        a0 += w * g_P[s * F + lane];
        a1 += w * g_P[s * F + 32 + lane];
    }
    float si = g_sin[node];
    float h0 = a0 * si + b1[lane];
    float h1 = a1 * si + b1[lane + 32];
    float so = g_sout[node];
    g_h1n[node * F + lane]       = h0 * so;
    g_h1n[node * F + 32 + lane]  = h1 * so;
}

// ---------------- gather 2: agg = segment_sum(h1n[src], dst)  (64 cols) -----
__global__ __launch_bounds__(256) void k_gather2() {
    int node = blockIdx.x * 8 + (threadIdx.x >> 5);
    if (node >= NN) return;
    int lane = threadIdx.x & 31;
    int beg = g_off[node];
    int cnt = g_cin[node];
    float a0 = 0.f, a1 = 0.f;
    int j = 0;
    for (; j + 4 <= cnt; j += 4) {
        int s0 = g_esrc[beg + j + 0];
        int s1 = g_esrc[beg + j + 1];
        int s2 = g_esrc[beg + j + 2];
        int s3 = g_esrc[beg + j + 3];
        a0 += g_h1n[s0 * F + lane];      a1 += g_h1n[s0 * F + 32 + lane];
        a0 += g_h1n[s1 * F + lane];      a1 += g_h1n[s1 * F + 32 + lane];
        a0 += g_h1n[s2 * F + lane];      a1 += g_h1n[s2 * F + 32 + lane];
        a0 += g_h1n[s3 * F + lane];      a1 += g_h1n[s3 * F + 32 + lane];
    }
    for (; j < cnt; j++) {
        int s = g_esrc[beg + j];
        a0 += g_h1n[s * F + lane];
        a1 += g_h1n[s * F + 32 + lane];
    }
    g_agg[node * F + lane]      = a0;
    g_agg[node * F + 32 + lane] = a1;
}

// ---------------- proj: [mu|logvar] = agg @ [Wmu|Wstd]; reparam; fp16 split -
__global__ __launch_bounds__(256) void k_proj(const float* __restrict__ eps,
                                              const float* __restrict__ Wmu,
                                              const float* __restrict__ bmu,
                                              const float* __restrict__ Wstd,
                                              const float* __restrict__ bstd,
                                              float* __restrict__ out) {
    __shared__ float sA[64][68];
    __shared__ float sW[64][128];   // reused as sOut after the k-loop
    int tid = threadIdx.x;
    int tx = tid & 15, ty = tid >> 4;
    int rowBase = blockIdx.x * 64;
    {
        int f4c = tid & 31;
        int k0 = tid >> 5;
#pragma unroll
        for (int it = 0; it < 8; it++) {
            int k = k0 + it * 8;
            float4 wv;
            if (f4c < 16) wv = *(const float4*)(Wmu + k * F + f4c * 4);
            else          wv = *(const float4*)(Wstd + k * F + (f4c - 16) * 4);
            *(float4*)&sW[k][f4c * 4] = wv;
        }
    }
#pragma unroll
    for (int it = 0; it < 4; it++) {
        int r = ty + it * 16;
        int gr = rowBase + r;
        float4 v = make_float4(0.f, 0.f, 0.f, 0.f);
        if (gr < NN) v = *(const float4*)&g_agg[gr * F + tx * 4];
        *(float4*)&sA[r][tx * 4] = v;
    }
    __syncthreads();
    float acc[4][8] = {};
#pragma unroll 8
    for (int kk = 0; kk < 64; kk++) {
        float a0 = sA[ty * 4 + 0][kk];
        float a1 = sA[ty * 4 + 1][kk];
        float a2 = sA[ty * 4 + 2][kk];
        float a3 = sA[ty * 4 + 3][kk];
        float4 b0 = *(float4*)&sW[kk][tx * 8];
        float4 b1 = *(float4*)&sW[kk][tx * 8 + 4];
        acc[0][0] += a0 * b0.x; acc[0][1] += a0 * b0.y; acc[0][2] += a0 * b0.z; acc[0][3] += a0 * b0.w;
        acc[0][4] += a0 * b1.x; acc[0][5] += a0 * b1.y; acc[0][6] += a0 * b1.z; acc[0][7] += a0 * b1.w;
        acc[1][0] += a1 * b0.x; acc[1][1] += a1 * b0.y; acc[1][2] += a1 * b0.z; acc[1][3] += a1 * b0.w;
        acc[1][4] += a1 * b1.x; acc[1][5] += a1 * b1.y; acc[1][6] += a1 * b1.z; acc[1][7] += a1 * b1.w;
        acc[2][0] += a2 * b0.x; acc[2][1] += a2 * b0.y; acc[2][2] += a2 * b0.z; acc[2][3] += a2 * b0.w;
        acc[2][4] += a2 * b1.x; acc[2][5] += a2 * b1.y; acc[2][6] += a2 * b1.z; acc[2][7] += a2 * b1.w;
        acc[3][0] += a3 * b0.x; acc[3][1] += a3 * b0.y; acc[3][2] += a3 * b0.z; acc[3][3] += a3 * b0.w;
        acc[3][4] += a3 * b1.x; acc[3][5] += a3 * b1.y; acc[3][6] += a3 * b1.z; acc[3][7] += a3 * b1.w;
    }
    __syncthreads();
    float (*sOut)[128] = (float (*)[128])sW;
#pragma unroll
    for (int i = 0; i < 4; i++) {
        *(float4*)&sOut[ty * 4 + i][tx * 8]     = make_float4(acc[i][0], acc[i][1], acc[i][2], acc[i][3]);
        *(float4*)&sOut[ty * 4 + i][tx * 8 + 4] = make_float4(acc[i][4], acc[i][5], acc[i][6], acc[i][7]);
    }
    __syncthreads();

    int w = tid >> 5;
    int lane = tid & 31;
    float bm0 = bmu[lane], bm1 = bmu[lane + 32];
    float bs0 = bstd[lane], bs1 = bstd[lane + 32];
#pragma unroll
    for (int i = 0; i < 8; i++) {
        int rloc = w * 8 + i;
        int node = rowBase + rloc;
        if (node >= NN) continue;
        float si = g_sin[node];
        float mu0 = sOut[rloc][lane]      * si + bm0;
        float mu1 = sOut[rloc][lane + 32] * si + bm1;
        float sd0 = __expf(sOut[rloc][64 + lane] * si + bs0);
        float sd1 = __expf(sOut[rloc][96 + lane] * si + bs1);
        out[MU_OFF + (size_t)node * F + lane]       = mu0;
        out[MU_OFF + (size_t)node * F + 32 + lane]  = mu1;
        out[STD_OFF + (size_t)node * F + lane]      = sd0;
        out[STD_OFF + (size_t)node * F + 32 + lane] = sd1;
        float z0 = eps[(size_t)node * F + lane]      * sd0 + mu0;
        float z1 = eps[(size_t)node * F + 32 + lane] * sd1 + mu1;
        __half h0 = __float2half_rn(z0);
        __half h1 = __float2half_rn(z1);
        __half l0 = __float2half_rn(z0 - __half2float(h0));
        __half l1 = __float2half_rn(z1 - __half2float(h1));
        __half* zr = &g_Z[(size_t)node * 128];
        zr[lane] = h0;       zr[lane + 32] = h1;    // chunk0 = h
        zr[64 + lane] = l0;  zr[96 + lane] = l1;    // chunk1 = l
    }
}

// ---------------- adj = sigmoid(Z Z^T), fp16x2, 256 thr, 16 warps/SM --------
#define KW     128
#define STRDB  272                       // bytes per smem row (256 data + 16 pad)
#define TILE_BYTES (128 * STRDB)         // 34816 B
#define ADJ_SMEM   (2 * TILE_BYTES)      // 69632 B
#define NPAN   79
#define NT_UT  (NPAN * (NPAN + 1) / 2)   // 3160
#define ADJ_GRID 296
#define ADJ_CHUNK ((NT_UT + ADJ_GRID - 1) / ADJ_GRID)  // 11

// A panel: chunks [h|l] at source offsets 0,128. B panel: [h|h] at 0,0.
// 2048 16B-chunks per panel, 256 threads -> 8 iters.
__device__ __forceinline__ void panel_cpasync(uint32_t smBase, const char* gBase,
                                              int rowBase, int tid,
                                              int off0, int off1) {
#pragma unroll
    for (int it = 0; it < 8; it++) {
        int idx = tid + it * 256;
        int r = idx >> 4;
        int cc = idx & 15;
        int srcOff = (cc < 8) ? off0 : off1;
        int g = cc & 7;
        int grow = rowBase + r;
        const char* src = gBase + (size_t)grow * 256 + srcOff + g * 16;
        int ss = (grow < NN) ? 16 : 0;
        cpasync16(smBase + r * STRDB + cc * 16, src, ss);
    }
}

__global__ __launch_bounds__(256, 2) void k_adj_hmma(float* __restrict__ out) {
    extern __shared__ char smem[];
    char* smA = smem;
    char* smB = smem + TILE_BYTES;
    uint32_t sbA = smem_u32(smA);
    uint32_t sbB = smem_u32(smB);

    int tid = threadIdx.x;
    int wid = tid >> 5, lane = tid & 31;
    int wm = wid & 3;        // 32-row quarter
    int wn = wid >> 2;       // 64-col half
    int group = lane >> 2;
    int qp = lane & 3;
    int lrow = lane & 15;
    int lkh  = (lane >> 4) * 16;

    int t0 = blockIdx.x * ADJ_CHUNK;
    int t1 = t0 + ADJ_CHUNK; if (t1 > NT_UT) t1 = NT_UT;
    if (t0 >= NT_UT) return;

    int p = 0, base = 0;
    while (base + (NPAN - p) <= t0) { base += NPAN - p; p++; }
    int c = p + (t0 - base);

    const char* Z = (const char*)g_Z;

    panel_cpasync(sbA, Z, p * 128, tid, 0, 128);   // [h|l]
    panel_cpasync(sbB, Z, c * 128, tid, 0, 0);     // [h|h]
    CP_COMMIT();
    CP_WAIT0();
    __syncthreads();

    for (int t = t0; t < t1; t++) {
        int rb = p * 128, cb = c * 128;

        float acc[2][8][4];
#pragma unroll
        for (int mt = 0; mt < 2; mt++)
#pragma unroll
            for (int nt = 0; nt < 8; nt++)
#pragma unroll
                for (int u = 0; u < 4; u++) acc[mt][nt][u] = 0.f;

#pragma unroll
        for (int ks = 0; ks < KW / 16; ks++) {
            int kb = ks * 32;
            uint32_t a[2][4];
#pragma unroll
            for (int mt = 0; mt < 2; mt++) {
                uint32_t addr = sbA + (wm * 32 + mt * 16 + lrow) * STRDB + kb + lkh;
                ldsm4(a[mt], addr);
            }
            uint32_t b[8][2];
#pragma unroll
            for (int bt = 0; bt < 4; bt++) {
                uint32_t tmp[4];
                uint32_t addr = sbB + (wn * 64 + bt * 16 + lrow) * STRDB + kb + lkh;
                ldsm4(tmp, addr);
                b[2 * bt][0] = tmp[0];     b[2 * bt][1] = tmp[2];
                b[2 * bt + 1][0] = tmp[1]; b[2 * bt + 1][1] = tmp[3];
            }
#pragma unroll
            for (int mt = 0; mt < 2; mt++)
#pragma unroll
                for (int nt = 0; nt < 8; nt++)
                    mma16816(acc[mt][nt], a[mt], b[nt]);
        }

        __syncthreads();

        int np = p, nc = c + 1;
        if (t + 1 < t1) {
            if (nc >= NPAN) { np = p + 1; nc = np; }
            if (np != p) panel_cpasync(sbA, Z, np * 128, tid, 0, 128);
            panel_cpasync(sbB, Z, nc * 128, tid, 0, 0);
            CP_COMMIT();
        }

        // sigmoid once (single-MUFU tanh form)
#pragma unroll
        for (int mt = 0; mt < 2; mt++)
#pragma unroll
            for (int nt = 0; nt < 8; nt++)
#pragma unroll
                for (int u = 0; u < 4; u++) acc[mt][nt][u] = sigf(acc[mt][nt][u]);

        // direct store (rb, cb)
#pragma unroll
        for (int mt = 0; mt < 2; mt++) {
            int r0 = rb + wm * 32 + mt * 16 + group;
            int r1 = r0 + 8;
            bool ok0 = r0 < NN, ok1 = r1 < NN;
            size_t ro0 = (size_t)r0 * NN, ro1 = (size_t)r1 * NN;
#pragma unroll
            for (int nt = 0; nt < 8; nt++) {
                int col = cb + wn * 64 + nt * 8 + qp * 2;
                if (col < NN) {
                    if (ok0) *(float2*)(out + ro0 + col) = make_float2(acc[mt][nt][0], acc[mt][nt][1]);
                    if (ok1) *(float2*)(out + ro1 + col) = make_float2(acc[mt][nt][2], acc[mt][nt][3]);
                }
            }
        }
        // mirrored store (cb, rb)
        if (p != c) {
#pragma unroll
            for (int mt = 0; mt < 2; mt++) {
                int r0 = rb + wm * 32 + mt * 16 + group;
                int r1 = r0 + 8;
                bool ok0 = r0 < NN, ok1 = r1 < NN;
#pragma unroll
                for (int nt = 0; nt < 8; nt++) {
                    int col = cb + wn * 64 + nt * 8 + qp * 2;
                    if (col < NN) {
                        if (ok0) out[(size_t)col * NN + r0] = acc[mt][nt][0];
                        if (ok1) out[(size_t)col * NN + r1] = acc[mt][nt][2];
                    }
                    if (col + 1 < NN) {
                        if (ok0) out[(size_t)(col + 1) * NN + r0] = acc[mt][nt][1];
                        if (ok1) out[(size_t)(col + 1) * NN + r1] = acc[mt][nt][3];
                    }
                }
            }
        }

        p = np; c = nc;
        CP_WAIT0();
        __syncthreads();
    }
}

// ---------------- launcher -------------------------------------------------
extern "C" void kernel_launch(void* const* d_in, const int* in_sizes, int n_in,
                              void* d_out, int out_size) {
    (void)in_sizes; (void)n_in; (void)out_size;
    const float* feat = (const float*)d_in[0];
    const float* eps  = (const float*)d_in[1];
    const int*   src  = (const int*)d_in[2];
    const int*   dst  = (const int*)d_in[3];
    const float* W1   = (const float*)d_in[4];
    const float* b1   = (const float*)d_in[5];
    const float* Wmu  = (const float*)d_in[6];
    const float* bmu  = (const float*)d_in[7];
    const float* Wstd = (const float*)d_in[8];
    const float* bstd = (const float*)d_in[9];
    float* out = (float*)d_out;

    static cudaStream_t s2 = nullptr;
    static cudaEvent_t evF = nullptr, evJ = nullptr;
    if (!s2) {
        cudaStreamCreateWithFlags(&s2, cudaStreamNonBlocking);
        cudaEventCreateWithFlags(&evF, cudaEventDisableTiming);
        cudaEventCreateWithFlags(&evJ, cudaEventDisableTiming);
        cudaFuncSetAttribute(k_adj_hmma, cudaFuncAttributeMaxDynamicSharedMemorySize, ADJ_SMEM);
    }

    // fork: CSR build on s2 runs parallel to gemm1 on the main stream
    cudaEventRecord(evF, 0);
    cudaStreamWaitEvent(s2, evF, 0);
    k_zero<<<(NN + 255) / 256, 256, 0, s2>>>();
    k_deg<<<(NE / 2 + 255) / 256, 256, 0, s2>>>(src, dst);
    k_scan<<<1, 1024, 0, s2>>>();
    k_scatter<<<(NE / 2 + 255) / 256, 256, 0, s2>>>(src, dst);
    cudaEventRecord(evJ, s2);

    k_gemm1<<<(NN + 63) / 64, 256>>>(feat, W1);

    cudaStreamWaitEvent(0, evJ, 0);
    k_gather1<<<(NN + 7) / 8, 256>>>(b1);
    k_gather2<<<(NN + 7) / 8, 256>>>();
    k_proj<<<(NN + 63) / 64, 256>>>(eps, Wmu, bmu, Wstd, bstd, out);
    k_adj_hmma<<<ADJ_GRID, 256, ADJ_SMEM>>>(out);
}